// round 8
// baseline (speedup 1.0000x reference)
#include <cuda_runtime.h>
#include <cuda_bf16.h>
#include <math.h>
#include <stdint.h>

#define N0    1000000
#define NN1   40960
#define NN2   4096
#define EE1   1024000
#define EE2   40960
#define IN_C  100
#define HID   256
#define OUT_C 47
#define CAP1  128
#define CAP2  64
#define KPAD  208          // 13 * 16

// ---------------- scratch (device globals; no allocation allowed) ----------------
__device__ int   g_is64;
__device__ int   g_cnt1[NN1];
__device__ int   g_cnt2[NN2];
__device__ int   g_bucket1[(size_t)NN1 * CAP1];
__device__ int   g_bucket2[(size_t)NN2 * CAP2];
__device__ float g_agg1[(size_t)NN1 * IN_C];
__device__ float g_h[(size_t)NN1 * HID];
__device__ float g_agg2[(size_t)NN2 * HID];
__device__ __align__(16) __nv_bfloat16 g_Bhi[(size_t)KPAD * HID];  // [k][n]
__device__ __align__(16) __nv_bfloat16 g_Blo[(size_t)KPAD * HID];

__device__ __forceinline__ int loadIdx(const void* p, int i, int is64) {
    return is64 ? (int)((const long long*)p)[i] : ((const int*)p)[i];
}
__device__ __forceinline__ uint32_t smem_u32(const void* p) {
    uint32_t a;
    asm("{ .reg .u64 t; cvta.to.shared.u64 t, %1; cvt.u32.u64 %0, t; }" : "=r"(a) : "l"(p));
    return a;
}
__device__ __forceinline__ uint32_t pack_bf2(__nv_bfloat16 a, __nv_bfloat16 b) {
    return (uint32_t)__bfloat16_as_ushort(a) | ((uint32_t)__bfloat16_as_ushort(b) << 16);
}

#define LDMX4(r0, r1, r2, r3, a) \
    asm volatile("ldmatrix.sync.aligned.m8n8.x4.shared.b16 {%0,%1,%2,%3}, [%4];" \
        : "=r"(r0), "=r"(r1), "=r"(r2), "=r"(r3) : "r"(a))
#define LDMX4T(r0, r1, r2, r3, a) \
    asm volatile("ldmatrix.sync.aligned.m8n8.x4.trans.shared.b16 {%0,%1,%2,%3}, [%4];" \
        : "=r"(r0), "=r"(r1), "=r"(r2), "=r"(r3) : "r"(a))
#define CPASYNC16(sa, gp) \
    asm volatile("cp.async.ca.shared.global [%0], [%1], 16;" :: "r"(sa), "l"(gp) : "memory")
#define CPCOMMIT() asm volatile("cp.async.commit_group;" ::: "memory")
#define CPWAIT0()  asm volatile("cp.async.wait_group 0;" ::: "memory")

__device__ __forceinline__ void mma16816(float* c, const uint32_t* a, uint32_t b0, uint32_t b1) {
    asm volatile("mma.sync.aligned.m16n8k16.row.col.f32.bf16.bf16.f32 "
        "{%0,%1,%2,%3}, {%4,%5,%6,%7}, {%8,%9}, {%0,%1,%2,%3};"
        : "+f"(c[0]), "+f"(c[1]), "+f"(c[2]), "+f"(c[3])
        : "r"(a[0]), "r"(a[1]), "r"(a[2]), "r"(a[3]), "r"(b0), "r"(b1));
}

// ---------------- init: zero counters + index dtype probe ----------------
__global__ void k_init(const void* src1) {
    int i = blockIdx.x * blockDim.x + threadIdx.x;
    if (i < NN1) g_cnt1[i] = 0;
    if (i < NN2) g_cnt2[i] = 0;
    if (i == 0) {
        const uint2* q = (const uint2*)src1;
        int is64 = 1;
        for (int k = 0; k < 64; k++) {
            if (q[k].y != 0u) { is64 = 0; break; }
        }
        g_is64 = is64;
    }
}

// ---------------- direct-bucket scatter ----------------
__global__ void k_scatter(const void* src1, const void* dst1,
                          const void* src2, const void* dst2) {
    int i = blockIdx.x * blockDim.x + threadIdx.x;
    int is64 = g_is64;
    if (i < EE1) {
        int d = loadIdx(dst1, i, is64);
        int pos = atomicAdd(&g_cnt1[d], 1);
        if (pos < CAP1) g_bucket1[(size_t)d * CAP1 + pos] = loadIdx(src1, i, is64);
    }
    if (i < EE2) {
        int d = loadIdx(dst2, i, is64);
        int pos = atomicAdd(&g_cnt2[d], 1);
        if (pos < CAP2) g_bucket2[(size_t)d * CAP2 + pos] = loadIdx(src2, i, is64);
    }
}

// ---------------- B hi/lo split build: [KPAD][HID] bf16, k-major ----------------
__global__ void k_prepB(const float* __restrict__ W1l, const float* __restrict__ W1r) {
    int idx = blockIdx.x * blockDim.x + threadIdx.x;
    if (idx >= KPAD * HID) return;
    int k = idx / HID, n = idx % HID;
    float w = 0.f;
    if (k < IN_C)            w = W1l[(size_t)k * HID + n];
    else if (k < 2 * IN_C)   w = W1r[(size_t)(k - IN_C) * HID + n];
    __nv_bfloat16 hi = __float2bfloat16(w);
    g_Bhi[idx] = hi;
    g_Blo[idx] = __float2bfloat16(w - __bfloat162float(hi));
}

// ---------------- layer 1 mean-aggregate ----------------
__global__ void k_agg1(const float* __restrict__ x) {
    int w    = (blockIdx.x * blockDim.x + threadIdx.x) >> 5;
    int lane = threadIdx.x & 31;
    if (w >= NN1) return;
    int cnt = g_cnt1[w];
    if (cnt > CAP1) cnt = CAP1;
    const int* bk = g_bucket1 + (size_t)w * CAP1;

    float4 acc = make_float4(0.f, 0.f, 0.f, 0.f);
    int i = 0;
    for (; i + 3 < cnt; i += 4) {
        int s0 = bk[i], s1 = bk[i + 1], s2 = bk[i + 2], s3 = bk[i + 3];
        if (lane < 25) {
            float4 v0 = ((const float4*)(x + (size_t)s0 * IN_C))[lane];
            float4 v1 = ((const float4*)(x + (size_t)s1 * IN_C))[lane];
            float4 v2 = ((const float4*)(x + (size_t)s2 * IN_C))[lane];
            float4 v3 = ((const float4*)(x + (size_t)s3 * IN_C))[lane];
            acc.x += (v0.x + v1.x) + (v2.x + v3.x);
            acc.y += (v0.y + v1.y) + (v2.y + v3.y);
            acc.z += (v0.z + v1.z) + (v2.z + v3.z);
            acc.w += (v0.w + v1.w) + (v2.w + v3.w);
        }
    }
    for (; i < cnt; i++) {
        int s0 = bk[i];
        if (lane < 25) {
            float4 v0 = ((const float4*)(x + (size_t)s0 * IN_C))[lane];
            acc.x += v0.x; acc.y += v0.y; acc.z += v0.z; acc.w += v0.w;
        }
    }
    float inv = 1.0f / (float)(cnt > 1 ? cnt : 1);
    if (lane < 25) {
        float4 o = make_float4(acc.x * inv, acc.y * inv, acc.z * inv, acc.w * inv);
        ((float4*)(g_agg1 + (size_t)w * IN_C))[lane] = o;
    }
}

// ---------------- GEMM1 via mma.sync bf16 3-term split, double-buffered pipeline ----
// h = relu([agg1|x] @ [W1l;W1r] + b1).  M=40960, N=256(BN=128), K=200->208.
// 256 threads = 8 warps (4 m x 2 n), warp tile 32x64, BK=16.
#define ASTRIDE 24     // bf16 elems per A smem row (16 + 8 pad), 48B
#define BSTRIDE 136    // bf16 elems per B smem row (128 + 8 pad), 272B
__global__ void __launch_bounds__(256) k_gemm1_mma(const float* __restrict__ x,
                                                   const float* __restrict__ b1l) {
    __shared__ __nv_bfloat16 Ahi[2][128 * ASTRIDE];
    __shared__ __nv_bfloat16 Alo[2][128 * ASTRIDE];
    __shared__ __nv_bfloat16 Bhi[2][16 * BSTRIDE];
    __shared__ __nv_bfloat16 Blo[2][16 * BSTRIDE];

    int tid  = threadIdx.x;
    int wid  = tid >> 5, lane = tid & 31;
    int wm   = wid & 3;
    int wn   = wid >> 2;
    int mbase = blockIdx.y * 128;
    int nbase = blockIdx.x * 128;

    float acc[2][8][4];
    #pragma unroll
    for (int a = 0; a < 2; a++)
        #pragma unroll
        for (int b = 0; b < 8; b++)
            #pragma unroll
            for (int c = 0; c < 4; c++) acc[a][b][c] = 0.f;

    int a_row  = tid >> 1;
    int a_c0   = (tid & 1) * 8;
    const float* aggrow = g_agg1 + (size_t)(mbase + a_row) * IN_C;
    const float* xrow   = x + (size_t)(mbase + a_row) * IN_C;
    int a_so = a_row * ASTRIDE + a_c0;

    int b_k   = tid >> 4;
    int b_c   = (tid & 15) * 8;
    int b_so  = b_k * BSTRIDE + b_c;

    uint32_t bhi_s[2], blo_s[2];
    bhi_s[0] = smem_u32(Bhi[0]) + b_so * 2;
    bhi_s[1] = smem_u32(Bhi[1]) + b_so * 2;
    blo_s[0] = smem_u32(Blo[0]) + b_so * 2;
    blo_s[1] = smem_u32(Blo[1]) + b_so * 2;

    uint32_t ahi_b[2] = { smem_u32(Ahi[0]), smem_u32(Ahi[1]) };
    uint32_t alo_b[2] = { smem_u32(Alo[0]), smem_u32(Alo[1]) };
    uint32_t bhi_b[2] = { smem_u32(Bhi[0]), smem_u32(Bhi[1]) };
    uint32_t blo_b[2] = { smem_u32(Blo[0]), smem_u32(Blo[1]) };

    uint32_t a_off[2];
    #pragma unroll
    for (int mb = 0; mb < 2; mb++)
        a_off[mb] = (uint32_t)((wm * 32 + mb * 16 + (lane & 15)) * (ASTRIDE * 2) + (lane >> 4) * 16);
    uint32_t b_off[4];
    #pragma unroll
    for (int gq = 0; gq < 4; gq++)
        b_off[gq] = (uint32_t)((lane & 15) * (BSTRIDE * 2) + (wn * 64 + gq * 16 + (lane >> 4) * 8) * 2);

    // ---- helpers as lambdas ----
    auto ldA = [&](int t, float4* va) {
        #pragma unroll
        for (int j = 0; j < 2; j++) {
            int kc = t * 16 + a_c0 + j * 4;
            va[j] = make_float4(0.f, 0.f, 0.f, 0.f);
            if (kc < 2 * IN_C)
                va[j] = *(const float4*)((kc < IN_C) ? (aggrow + kc) : (xrow + kc - IN_C));
        }
    };
    auto stA = [&](int buf, const float4* va) {
        #pragma unroll
        for (int j = 0; j < 2; j++) {
            float4 v = va[j];
            __nv_bfloat16 h0 = __float2bfloat16(v.x), h1 = __float2bfloat16(v.y);
            __nv_bfloat16 h2 = __float2bfloat16(v.z), h3 = __float2bfloat16(v.w);
            __nv_bfloat16 l0 = __float2bfloat16(v.x - __bfloat162float(h0));
            __nv_bfloat16 l1 = __float2bfloat16(v.y - __bfloat162float(h1));
            __nv_bfloat16 l2 = __float2bfloat16(v.z - __bfloat162float(h2));
            __nv_bfloat16 l3 = __float2bfloat16(v.w - __bfloat162float(h3));
            *(uint2*)&Ahi[buf][a_so + j * 4] = make_uint2(pack_bf2(h0, h1), pack_bf2(h2, h3));
            *(uint2*)&Alo[buf][a_so + j * 4] = make_uint2(pack_bf2(l0, l1), pack_bf2(l2, l3));
        }
    };
    auto ldB = [&](int t, int buf) {
        size_t go = (size_t)(t * 16 + b_k) * HID + nbase + b_c;
        CPASYNC16(bhi_s[buf], (const char*)&g_Bhi[go]);
        CPASYNC16(blo_s[buf], (const char*)&g_Blo[go]);
        CPCOMMIT();
    };

    // ---- prologue: stage chunk 0 into buf 0 ----
    float4 va[2];
    ldA(0, va);
    ldB(0, 0);
    stA(0, va);
    CPWAIT0();
    __syncthreads();

    for (int t = 0; t < 13; t++) {
        int cur = t & 1, nxt = cur ^ 1;
        bool more = (t < 12);
        if (more) {
            ldA(t + 1, va);          // LDGs issue early, land during mma
            ldB(t + 1, nxt);         // cp.async into other buffer
        }

        // ---- fragments + mma from buf cur ----
        uint32_t ah[2][4], al[2][4], bf[4][4];
        #pragma unroll
        for (int mb = 0; mb < 2; mb++) {
            LDMX4(ah[mb][0], ah[mb][1], ah[mb][2], ah[mb][3], ahi_b[cur] + a_off[mb]);
            LDMX4(al[mb][0], al[mb][1], al[mb][2], al[mb][3], alo_b[cur] + a_off[mb]);
        }
        #pragma unroll
        for (int gq = 0; gq < 4; gq++)
            LDMX4T(bf[gq][0], bf[gq][1], bf[gq][2], bf[gq][3], bhi_b[cur] + b_off[gq]);
        #pragma unroll
        for (int mb = 0; mb < 2; mb++)
            #pragma unroll
            for (int gq = 0; gq < 4; gq++) {
                mma16816(acc[mb][gq * 2 + 0], ah[mb], bf[gq][0], bf[gq][1]);
                mma16816(acc[mb][gq * 2 + 1], ah[mb], bf[gq][2], bf[gq][3]);
                mma16816(acc[mb][gq * 2 + 0], al[mb], bf[gq][0], bf[gq][1]);
                mma16816(acc[mb][gq * 2 + 1], al[mb], bf[gq][2], bf[gq][3]);
            }
        #pragma unroll
        for (int gq = 0; gq < 4; gq++)
            LDMX4T(bf[gq][0], bf[gq][1], bf[gq][2], bf[gq][3], blo_b[cur] + b_off[gq]);
        #pragma unroll
        for (int mb = 0; mb < 2; mb++)
            #pragma unroll
            for (int gq = 0; gq < 4; gq++) {
                mma16816(acc[mb][gq * 2 + 0], ah[mb], bf[gq][0], bf[gq][1]);
                mma16816(acc[mb][gq * 2 + 1], ah[mb], bf[gq][2], bf[gq][3]);
            }

        if (more) {
            stA(nxt, va);            // convert + store next A
            CPWAIT0();               // next B landed
        }
        __syncthreads();
    }

    // ---- epilogue: bias + relu ----
    #pragma unroll
    for (int mb = 0; mb < 2; mb++) {
        int row0 = mbase + wm * 32 + mb * 16 + (lane >> 2);
        #pragma unroll
        for (int nb = 0; nb < 8; nb++) {
            int col = nbase + wn * 64 + nb * 8 + (lane & 3) * 2;
            float2 bias = *(const float2*)&b1l[col];
            float2 o0, o1;
            o0.x = fmaxf(acc[mb][nb][0] + bias.x, 0.f);
            o0.y = fmaxf(acc[mb][nb][1] + bias.y, 0.f);
            o1.x = fmaxf(acc[mb][nb][2] + bias.x, 0.f);
            o1.y = fmaxf(acc[mb][nb][3] + bias.y, 0.f);
            *(float2*)&g_h[(size_t)row0 * HID + col]       = o0;
            *(float2*)&g_h[(size_t)(row0 + 8) * HID + col] = o1;
        }
    }
}

// ---------------- layer 2 mean-aggregate ----------------
__global__ void k_agg2() {
    int w    = (blockIdx.x * blockDim.x + threadIdx.x) >> 5;
    int lane = threadIdx.x & 31;
    if (w >= NN2) return;
    int cnt = g_cnt2[w];
    if (cnt > CAP2) cnt = CAP2;
    const int* bk = g_bucket2 + (size_t)w * CAP2;

    float4 a0 = make_float4(0.f, 0.f, 0.f, 0.f);
    float4 a1 = make_float4(0.f, 0.f, 0.f, 0.f);
    for (int i = 0; i < cnt; i++) {
        int s = bk[i];
        const float4* r = (const float4*)(g_h + (size_t)s * HID);
        float4 v0 = r[lane];
        float4 v1 = r[lane + 32];
        a0.x += v0.x; a0.y += v0.y; a0.z += v0.z; a0.w += v0.w;
        a1.x += v1.x; a1.y += v1.y; a1.z += v1.z; a1.w += v1.w;
    }
    float inv = 1.0f / (float)(cnt > 1 ? cnt : 1);
    float4* o = (float4*)(g_agg2 + (size_t)w * HID);
    o[lane]      = make_float4(a0.x * inv, a0.y * inv, a0.z * inv, a0.w * inv);
    o[lane + 32] = make_float4(a1.x * inv, a1.y * inv, a1.z * inv, a1.w * inv);
}

// ---------------- final: out = log_softmax(agg2@W2l + b2 + h_dst@W2r) ----------------
__global__ void __launch_bounds__(256) k_final(const float* __restrict__ W2l,
                                               const float* __restrict__ b2l,
                                               const float* __restrict__ W2r,
                                               float* __restrict__ out) {
    __shared__ float abuf[8][512];
    int w    = threadIdx.x >> 5;
    int lane = threadIdx.x & 31;
    int r    = blockIdx.x * 8 + w;

    float* a = abuf[w];
    const float* agg = g_agg2 + (size_t)r * HID;
    const float* hd  = g_h    + (size_t)r * HID;
    #pragma unroll
    for (int j = 0; j < 8; j++) {
        a[lane + 32 * j]       = agg[lane + 32 * j];
        a[256 + lane + 32 * j] = hd[lane + 32 * j];
    }
    __syncwarp();

    int o1 = lane;
    int o2 = lane + 32;
    bool v2 = (o2 < OUT_C);
    float acc1 = b2l[o1];
    float acc2 = v2 ? b2l[o2] : 0.f;

    #pragma unroll 4
    for (int k = 0; k < HID; k++) {
        float av = a[k];
        const float* Bk = W2l + (size_t)k * OUT_C;
        acc1 += av * Bk[o1];
        if (v2) acc2 += av * Bk[o2];
    }
    #pragma unroll 4
    for (int k = 0; k < HID; k++) {
        float av = a[256 + k];
        const float* Bk = W2r + (size_t)k * OUT_C;
        acc1 += av * Bk[o1];
        if (v2) acc2 += av * Bk[o2];
    }

    float m = v2 ? fmaxf(acc1, acc2) : acc1;
    #pragma unroll
    for (int s = 16; s; s >>= 1) m = fmaxf(m, __shfl_xor_sync(0xffffffffu, m, s));
    float e = expf(acc1 - m) + (v2 ? expf(acc2 - m) : 0.f);
    #pragma unroll
    for (int s = 16; s; s >>= 1) e += __shfl_xor_sync(0xffffffffu, e, s);
    float ls = logf(e);

    out[(size_t)r * OUT_C + o1] = acc1 - m - ls;
    if (v2) out[(size_t)r * OUT_C + o2] = acc2 - m - ls;
}

// ---------------- launch ----------------
extern "C" void kernel_launch(void* const* d_in, const int* in_sizes, int n_in,
                              void* d_out, int out_size) {
    const float* x   = (const float*)d_in[0];
    const float* W1l = (const float*)d_in[1];
    const float* b1l = (const float*)d_in[2];
    const float* W1r = (const float*)d_in[3];
    const float* W2l = (const float*)d_in[4];
    const float* b2l = (const float*)d_in[5];
    const float* W2r = (const float*)d_in[6];
    const void*  src1 = d_in[7];
    const void*  dst1 = d_in[8];
    const void*  src2 = d_in[9];
    const void*  dst2 = d_in[10];
    float* out = (float*)d_out;

    k_init<<<(NN1 + 255) / 256, 256>>>(src1);
    k_prepB<<<(KPAD * HID + 255) / 256, 256>>>(W1l, W1r);
    k_scatter<<<(EE1 + 255) / 256, 256>>>(src1, dst1, src2, dst2);
    k_agg1<<<NN1 / 8, 256>>>(x);
    k_gemm1_mma<<<dim3(2, NN1 / 128), 256>>>(x, b1l);
    k_agg2<<<NN2 / 8, 256>>>();
    k_final<<<NN2 / 8, 256>>>(W2l, b2l, W2r, out);
}